// round 3
// baseline (speedup 1.0000x reference)
#include <cuda_runtime.h>

// B=2048 rows, N=8192 cols.
// Per row: r = |y_true - y_pred|; solve mean(sinh(r/eps))=1 via Newton in
// beta=1/eps on h(beta)=log(mean sinh(beta*r)) (same unique root as the
// reference's 20 eps-space Newton iterations, converged well past the 1e-3
// tolerance): 2 cheap warm-start iterations (exp(+x) only), then full
// iterations with early exit; the final iteration's exps are reused as q.
// q_norm = q/(sinh(beta*rmax)+1e-20) (sinh monotone => elementwise max);
// Lambda' = 0.99*Lambda + 0.1*(0.9*q_norm + 0.1);
// loss = mean((Lambda' * r)^2), reduced in-kernel by the last block.
// Output: d_out[0] = loss, d_out[1..B*N] = Lambda' (row-major).

#define BDIM 1024
#define VPT 8

static constexpr int B = 2048;
static constexpr int N = 8192;
static constexpr float LOG_2N = 9.70406052783923f;  // ln(2*N) = ln(16384)

__device__ float g_row_loss[B];
__device__ unsigned int g_count = 0;

__device__ __forceinline__ float warp_sum(float v) {
#pragma unroll
    for (int o = 16; o; o >>= 1) v += __shfl_xor_sync(0xffffffffu, v, o);
    return v;
}
__device__ __forceinline__ float warp_max(float v) {
#pragma unroll
    for (int o = 16; o; o >>= 1) v = fmaxf(v, __shfl_xor_sync(0xffffffffu, v, o));
    return v;
}

__global__ __launch_bounds__(BDIM)
void custom_loss_row_kernel(const float* __restrict__ y_pred,
                            const float* __restrict__ y_true,
                            const float* __restrict__ Lam,
                            float* __restrict__ out_lambda,
                            float* __restrict__ out_loss) {
    const int b = blockIdx.x;
    const size_t base = (size_t)b * N;
    const int t = threadIdx.x;
    const int lane = t & 31;
    const int wid = t >> 5;

    __shared__ float s1s[32];
    __shared__ float s2s[32];
    __shared__ float bcast;
    __shared__ int   sdone;

    // ---- residuals: float4 loads, 8 elems/thread ----
    const float4* yp4 = (const float4*)(y_pred + base);
    const float4* yt4 = (const float4*)(y_true + base);
    const float4 p0 = yp4[t],        g0 = yt4[t];
    const float4 p1 = yp4[t + BDIM], g1 = yt4[t + BDIM];
    float r[VPT];
    r[0] = fabsf(g0.x - p0.x); r[1] = fabsf(g0.y - p0.y);
    r[2] = fabsf(g0.z - p0.z); r[3] = fabsf(g0.w - p0.w);
    r[4] = fabsf(g1.x - p1.x); r[5] = fabsf(g1.y - p1.y);
    r[6] = fabsf(g1.z - p1.z); r[7] = fabsf(g1.w - p1.w);

    // L2 prefetch Lambda (consumed after the Newton loop; no register cost)
    {
        const float4* L4 = (const float4*)(Lam + base);
        asm volatile("prefetch.global.L2 [%0];" :: "l"(L4 + t));
        asm volatile("prefetch.global.L2 [%0];" :: "l"(L4 + t + BDIM));
    }

    // ---- row max(r) ----
    float m = r[0];
#pragma unroll
    for (int i = 1; i < VPT; i++) m = fmaxf(m, r[i]);
    m = warp_max(m);
    if (lane == 0) s1s[wid] = m;
    __syncthreads();
    if (t < 32) {
        float v = warp_max(s1s[t]);
        if (t == 0) bcast = v;
    }
    __syncthreads();
    const float rmax = bcast;

    // beta0 = 1/eps0, eps0 = max(rmax,1e-8)/(ln(2N)+1e-8)  (reference init)
    float beta = (LOG_2N + 1e-8f) / fmaxf(rmax, 1e-8f);

    // ---- phase 1: 2 cheap warm-start Newton iterations (exp(+x) only) ----
    // Solves sum(e^{beta*r}) = 2N; root ~1% below the true root. log-sum-exp
    // is convex increasing => monotone convergence, beta stays <= beta0.
#pragma unroll 1
    for (int itn = 0; itn < 2; itn++) {
        float S = 0.0f;  // sum e^x
        float T = 0.0f;  // sum r * e^x
#pragma unroll
        for (int i = 0; i < VPT; i++) {
            const float E = __expf(beta * r[i]);
            S += E;
            T = fmaf(E, r[i], T);
        }
        S = warp_sum(S);
        T = warp_sum(T);
        if (lane == 0) { s1s[wid] = S; s2s[wid] = T; }
        __syncthreads();
        if (t < 32) {
            float S2 = warp_sum(s1s[t]);
            float T2 = warp_sum(s2s[t]);
            if (t == 0) {
                const float h  = __logf(S2) - LOG_2N;
                const float db = h * __fdividef(S2, T2);
                float nb = beta - db;
                nb = fminf(fmaxf(nb, 0.05f * beta), 4.0f * beta);  // safety
                bcast = nb;
            }
        }
        __syncthreads();
        beta = bcast;
    }

    // ---- phase 2: full Newton on h(beta)=log(sum(e^x - e^-x)) - ln(2N) ----
    // Early exit at |db| < 1e-5*beta; the last-evaluated iteration's exps are
    // therefore already within 1e-5 (relative, in beta) of the converged root
    // and are reused below as q = sinh.
    float sh[VPT];          // E - Em from the last evaluated iteration
    float beta_eval = beta; // beta at which sh[] was evaluated
#pragma unroll 1
    for (int itn = 0; itn < 12; itn++) {
        beta_eval = beta;
        float S = 0.0f;  // sum (e^x - e^-x) = 2*sum sinh
        float T = 0.0f;  // sum r*(e^x + e^-x) = 2*sum r*cosh
#pragma unroll
        for (int i = 0; i < VPT; i++) {
            const float x  = beta * r[i];
            const float E  = __expf(x);
            const float Em = __expf(-x);
            sh[i] = E - Em;
            S += sh[i];
            T = fmaf(E + Em, r[i], T);
        }
        S = warp_sum(S);
        T = warp_sum(T);
        if (lane == 0) { s1s[wid] = S; s2s[wid] = T; }
        __syncthreads();
        if (t < 32) {
            float S2 = warp_sum(s1s[t]);
            float T2 = warp_sum(s2s[t]);
            if (t == 0) {
                const float h  = __logf(S2) - LOG_2N;
                const float db = h * __fdividef(S2, T2);
                float nb = beta - db;
                nb = fminf(fmaxf(nb, 0.05f * beta), 4.0f * beta);  // safety
                bcast = nb;
                sdone = (fabsf(db) < 1e-5f * beta) ? 1 : 0;
            }
        }
        __syncthreads();
        beta = bcast;
        if (sdone) break;  // uniform across block
    }

    // q = sinh(beta_eval * r) from saved exps; qmax analytically at rmax
    // (sinh monotone on r>=0). beta_eval is within ~1e-5 rel of the
    // reference's converged 1/(eps+1e-6); effect on Lambda is ~1e-5 abs.
    const float xm = beta_eval * rmax;
    const float qmax = 0.5f * (__expf(xm) - __expf(-xm));
    const float inv_qm = __fdividef(1.0f, qmax + 1e-20f);

    // ---- Lambda update (float4 loads; scalar stores: out base is +1 float,
    //      so 16B-misaligned) + per-row loss partial ----
    const float4* L4 = (const float4*)(Lam + base);
    const float4 l0 = L4[t], l1 = L4[t + BDIM];
    const float lamv[VPT] = {l0.x, l0.y, l0.z, l0.w, l1.x, l1.y, l1.z, l1.w};

    float lsum = 0.0f;
#pragma unroll
    for (int i = 0; i < VPT; i++) {
        const int idx = (i < 4) ? (4 * t + i) : (4 * (t + BDIM) + (i - 4));
        const float qn = 0.5f * sh[i] * inv_qm;
        const float lam_it = fmaf(0.9f, qn, 0.1f);              // PHI*qn + (1-PHI)
        const float lam = fmaf(0.99f, lamv[i], 0.1f * lam_it);  // GAMMA*L + ETA*lam_it
        out_lambda[base + idx] = lam;
        const float z = lam * r[i];
        lsum = fmaf(z, z, lsum);
    }
    lsum = warp_sum(lsum);
    if (lane == 0) s1s[wid] = lsum;
    __syncthreads();
    if (t < 32) {
        float v = warp_sum(s1s[t]);
        if (t == 0) g_row_loss[b] = v;
    }

    // ---- last block reduces the per-row partials (threadFenceReduction
    //      pattern; deterministic fixed-order sum; counter self-resets so
    //      every graph replay behaves identically) ----
    __shared__ int amLast;
    __threadfence();
    if (t == 0) {
        const unsigned int v = atomicAdd(&g_count, 1u);
        amLast = (v == (unsigned int)(B - 1));
    }
    __syncthreads();
    if (amLast) {
        float s = g_row_loss[t] + g_row_loss[t + BDIM];
        s = warp_sum(s);
        if (lane == 0) s2s[wid] = s;
        __syncthreads();
        if (t < 32) {
            float v = warp_sum(s2s[t]);
            if (t == 0) {
                out_loss[0] = v * (1.0f / 16777216.0f);  // / (B*N)
                g_count = 0;  // reset for next launch/replay
            }
        }
    }
}

extern "C" void kernel_launch(void* const* d_in, const int* in_sizes, int n_in,
                              void* d_out, int out_size) {
    const float* y_pred = (const float*)d_in[0];
    const float* y_true = (const float*)d_in[1];
    const float* Lam    = (const float*)d_in[2];
    // d_in[3] = it (unused by the cosh branch)

    float* out = (float*)d_out;       // out[0] = loss
    float* out_lambda = out + 1;      // out[1..] = updated Lambda

    custom_loss_row_kernel<<<B, BDIM>>>(y_pred, y_true, Lam, out_lambda, out);
}

// round 4
// speedup vs baseline: 1.5363x; 1.5363x over previous
#include <cuda_runtime.h>

// B=2048 rows, N=8192 cols.
// Per row: r = |y_true - y_pred|; solve mean(sinh(r/eps))=1 via damped-Halley
// iteration in beta=1/eps on h(beta)=log(sum sinh(beta*r)) - ln(2N) (same
// unique root as the reference's 20 eps-space Newton iterations; cubic
// convergence, early exit at |step| < 1e-5*beta). The final iteration's
// exps are reused as q = sinh(beta*r); qmax = sinh(beta*rmax) analytically
// (sinh monotone on r>=0). q_norm = q/(qmax+1e-20);
// Lambda' = 0.99*Lambda + 0.1*(0.9*q_norm + 0.1);
// loss = mean((Lambda' * r)^2)  (per-row partials + tiny second kernel).
// Output: d_out[0] = loss, d_out[1..B*N] = Lambda' (row-major).

#define BDIM 1024
#define VPT 8

static constexpr int B = 2048;
static constexpr int N = 8192;
static constexpr float LOG_2N = 9.70406052783923f;  // ln(2*N) = ln(16384)

__device__ float g_row_loss[B];

__device__ __forceinline__ float warp_sum(float v) {
#pragma unroll
    for (int o = 16; o; o >>= 1) v += __shfl_xor_sync(0xffffffffu, v, o);
    return v;
}
__device__ __forceinline__ float warp_max(float v) {
#pragma unroll
    for (int o = 16; o; o >>= 1) v = fmaxf(v, __shfl_xor_sync(0xffffffffu, v, o));
    return v;
}

__global__ __launch_bounds__(BDIM)
void custom_loss_row_kernel(const float* __restrict__ y_pred,
                            const float* __restrict__ y_true,
                            const float* __restrict__ Lam,
                            float* __restrict__ out_lambda) {
    const int b = blockIdx.x;
    const size_t base = (size_t)b * N;
    const int t = threadIdx.x;
    const int lane = t & 31;
    const int wid = t >> 5;

    __shared__ float s1s[32];
    __shared__ float s2s[32];
    __shared__ float s3s[32];
    __shared__ float bcast;
    __shared__ int   sdone;

    // ---- residuals: float4 loads, 8 elems/thread ----
    const float4* yp4 = (const float4*)(y_pred + base);
    const float4* yt4 = (const float4*)(y_true + base);
    const float4 p0 = yp4[t],        g0 = yt4[t];
    const float4 p1 = yp4[t + BDIM], g1 = yt4[t + BDIM];
    float r[VPT];
    r[0] = fabsf(g0.x - p0.x); r[1] = fabsf(g0.y - p0.y);
    r[2] = fabsf(g0.z - p0.z); r[3] = fabsf(g0.w - p0.w);
    r[4] = fabsf(g1.x - p1.x); r[5] = fabsf(g1.y - p1.y);
    r[6] = fabsf(g1.z - p1.z); r[7] = fabsf(g1.w - p1.w);

    // ---- row max(r) ----
    float m = r[0];
#pragma unroll
    for (int i = 1; i < VPT; i++) m = fmaxf(m, r[i]);
    m = warp_max(m);
    if (lane == 0) s1s[wid] = m;
    __syncthreads();
    if (t < 32) {
        float v = warp_max(s1s[t]);
        if (t == 0) bcast = v;
    }
    __syncthreads();
    const float rmax = bcast;

    // beta0 = 1/eps0, eps0 = max(rmax,1e-8)/(ln(2N)+1e-8)  (reference init;
    // beta0 is at/above the root -> first step moves down, monotone region)
    float beta = (LOG_2N + 1e-8f) / fmaxf(rmax, 1e-8f);

    // ---- damped Halley on h(beta) = log(S) - ln(2N),  S = sum(e^x - e^-x) ----
    // h' = T/S (T = sum r*(e^x+e^-x));  h'' = U/S - (T/S)^2 (U = sum r^2*(e^x-e^-x)).
    // Halley: beta+ = beta - (h/h') / (1 - h*h''/(2 h'^2)), correction clamped
    // to [0.5, 2] => never worse than damped Newton; cubic near the root.
    float sh[VPT];          // E - Em from the last evaluated iteration
    float beta_eval = beta;
#pragma unroll 1
    for (int itn = 0; itn < 12; itn++) {
        beta_eval = beta;
        float S = 0.0f, T = 0.0f, U = 0.0f;
#pragma unroll
        for (int i = 0; i < VPT; i++) {
            const float x  = beta * r[i];
            const float E  = __expf(x);
            const float Em = __expf(-x);
            const float d  = E - Em;
            sh[i] = d;
            S += d;
            T = fmaf(E + Em, r[i], T);
            U = fmaf(d * r[i], r[i], U);
        }
        S = warp_sum(S);
        T = warp_sum(T);
        U = warp_sum(U);
        if (lane == 0) { s1s[wid] = S; s2s[wid] = T; s3s[wid] = U; }
        __syncthreads();
        if (t < 32) {
            float S2 = warp_sum(s1s[t]);
            float T2 = warp_sum(s2s[t]);
            float U2 = warp_sum(s3s[t]);
            if (t == 0) {
                const float h   = __logf(S2) - LOG_2N;
                const float hp  = __fdividef(T2, S2);            // h'
                const float hpp = __fdividef(U2, S2) - hp * hp;  // h''
                const float tN  = __fdividef(h, hp);             // Newton step
                float corr = 1.0f - 0.5f * tN * __fdividef(hpp, hp);
                corr = fminf(fmaxf(corr, 0.5f), 2.0f);
                const float db = __fdividef(tN, corr);
                float nb = beta - db;
                nb = fminf(fmaxf(nb, 0.05f * beta), 4.0f * beta);  // safety
                bcast = nb;
                sdone = (fabsf(db) < 1e-5f * beta) ? 1 : 0;
            }
        }
        __syncthreads();
        beta = bcast;
        if (sdone) break;  // uniform across block
    }

    // q = sinh(beta_eval*r) from saved exps (beta_eval within 1e-5 rel of the
    // converged root; the reference's extra +1e-6 on eps shifts beta by ~2e-6
    // rel -> both effects ~1e-4 on q_norm, ~1e-5 abs on Lambda).
    const float xm = beta_eval * rmax;
    const float qmax = 0.5f * (__expf(xm) - __expf(-xm));
    const float inv_qm = __fdividef(1.0f, qmax + 1e-20f);

    // ---- Lambda update (float4 loads; scalar stores: out base is +1 float,
    //      so 16B-misaligned) + per-row loss partial ----
    const float4* L4 = (const float4*)(Lam + base);
    const float4 l0 = L4[t], l1 = L4[t + BDIM];

    float lsum = 0.0f;
    {
        const float la[VPT] = {l0.x, l0.y, l0.z, l0.w, l1.x, l1.y, l1.z, l1.w};
#pragma unroll
        for (int i = 0; i < VPT; i++) {
            const int idx = (i < 4) ? (4 * t + i) : (4 * (t + BDIM) + (i - 4));
            const float qn = 0.5f * sh[i] * inv_qm;
            const float lam_it = fmaf(0.9f, qn, 0.1f);              // PHI*qn + (1-PHI)
            const float lam = fmaf(0.99f, la[i], 0.1f * lam_it);    // GAMMA*L + ETA*lam_it
            out_lambda[base + idx] = lam;
            const float z = lam * r[i];
            lsum = fmaf(z, z, lsum);
        }
    }
    lsum = warp_sum(lsum);
    if (lane == 0) s1s[wid] = lsum;
    __syncthreads();
    if (t < 32) {
        float v = warp_sum(s1s[t]);
        if (t == 0) g_row_loss[b] = v;
    }
}

__global__ void loss_reduce_kernel(float* __restrict__ out_loss) {
    const int t = threadIdx.x;  // 1024 threads
    float s = g_row_loss[t] + g_row_loss[t + 1024];
    s = warp_sum(s);
    __shared__ float sm[32];
    if ((t & 31) == 0) sm[t >> 5] = s;
    __syncthreads();
    if (t < 32) {
        float v = warp_sum(sm[t]);
        if (t == 0) out_loss[0] = v * (1.0f / 16777216.0f);  // / (B*N)
    }
}

extern "C" void kernel_launch(void* const* d_in, const int* in_sizes, int n_in,
                              void* d_out, int out_size) {
    const float* y_pred = (const float*)d_in[0];
    const float* y_true = (const float*)d_in[1];
    const float* Lam    = (const float*)d_in[2];
    // d_in[3] = it (unused by the cosh branch)

    float* out = (float*)d_out;       // out[0] = loss
    float* out_lambda = out + 1;      // out[1..] = updated Lambda

    custom_loss_row_kernel<<<B, BDIM>>>(y_pred, y_true, Lam, out_lambda);
    loss_reduce_kernel<<<1, BDIM>>>(out);
}